// round 14
// baseline (speedup 1.0000x reference)
#include <cuda_runtime.h>
#include <cuda_bf16.h>
#include <cstdint>
#include <cstddef>

#define BSZ   32
#define TT    512
#define HH    512
#define G4    2048
#define SGRPS 2            // supergroups
#define GCTAS 32           // CTAs per supergroup
#define NCTA_REC (SGRPS*GCTAS)   // 64
#define NTHR  512

// Device statics: identical set to passing R7/R10/R13.
__device__ float g_xg[(size_t)TT * BSZ * G4];     // [T][B][4H]
__device__ float g_h[2][BSZ * HH];                // double-buffered h, [b][j]
__device__ unsigned g_bar4[4 * 32];               // 4 counters (sg,set), 128B apart

// ---------- packed fp32x2 helpers ----------
__device__ __forceinline__ unsigned long long pack2(float lo, float hi) {
    unsigned long long r;
    asm("mov.b64 %0, {%1, %2};" : "=l"(r) : "f"(lo), "f"(hi));
    return r;
}
__device__ __forceinline__ void unpack2(unsigned long long v, float& lo, float& hi) {
    asm("mov.b64 {%0, %1}, %2;" : "=f"(lo), "=f"(hi) : "l"(v));
}
__device__ __forceinline__ void ffma2(unsigned long long& d,
                                      unsigned long long a,
                                      unsigned long long b) {
    asm("fma.rn.f32x2 %0, %1, %2, %0;" : "+l"(d) : "l"(a), "l"(b));
}
__device__ __forceinline__ float fast_sigmoid(float x) {
    return __fdividef(1.f, 1.f + __expf(-x));
}
__device__ __forceinline__ float fast_tanh(float x) {
    x = fminf(fmaxf(x, -15.f), 15.f);
    float e2 = __expf(-2.f * x);
    return __fdividef(1.f - e2, 1.f + e2);
}

__device__ __forceinline__ void mma_bf16(float4& c, const uint4& a, const uint2& b) {
    asm("mma.sync.aligned.m16n8k16.row.col.f32.bf16.bf16.f32 "
        "{%0,%1,%2,%3}, {%4,%5,%6,%7}, {%8,%9}, {%0,%1,%2,%3};"
        : "+f"(c.x), "+f"(c.y), "+f"(c.z), "+f"(c.w)
        : "r"(a.x), "r"(a.y), "r"(a.z), "r"(a.w), "r"(b.x), "r"(b.y));
}

__device__ __forceinline__ void cvt_split(float4 v, uint2& hi, uint2& lo) {
    __nv_bfloat16 hx = __float2bfloat16(v.x);
    __nv_bfloat16 hy = __float2bfloat16(v.y);
    __nv_bfloat16 hz = __float2bfloat16(v.z);
    __nv_bfloat16 hw = __float2bfloat16(v.w);
    __nv_bfloat162 h01 = __halves2bfloat162(hx, hy);
    __nv_bfloat162 h23 = __halves2bfloat162(hz, hw);
    __nv_bfloat162 l01 = __halves2bfloat162(
        __float2bfloat16(v.x - __bfloat162float(hx)),
        __float2bfloat16(v.y - __bfloat162float(hy)));
    __nv_bfloat162 l23 = __halves2bfloat162(
        __float2bfloat16(v.z - __bfloat162float(hz)),
        __float2bfloat16(v.w - __bfloat162float(hw)));
    hi.x = *reinterpret_cast<unsigned*>(&h01);
    hi.y = *reinterpret_cast<unsigned*>(&h23);
    lo.x = *reinterpret_cast<unsigned*>(&l01);
    lo.y = *reinterpret_cast<unsigned*>(&l23);
}

// =====================================================================
// Phase 1: bf16x3 tensor-core GEMM with in-kernel split (R13, passed).
// =====================================================================
#define AST 40

__global__ void __launch_bounds__(256) gemm_xg_mma(
    const float* __restrict__ x,
    const float* __restrict__ Wih,
    const float* __restrict__ bih,
    const float* __restrict__ bhh)
{
    __shared__ __nv_bfloat16 AsH[128 * AST];
    __shared__ __nv_bfloat16 AsL[128 * AST];
    __shared__ __nv_bfloat16 BsH[128 * AST];
    __shared__ __nv_bfloat16 BsL[128 * AST];

    const int tid    = threadIdx.x;
    const int m0     = blockIdx.x * 128;
    const int n0     = blockIdx.y * 128;
    const int wid    = tid >> 5;
    const int lane   = tid & 31;
    const int warp_m = wid & 3;
    const int warp_n = wid >> 2;
    const int gq     = lane >> 2;
    const int t4     = lane & 3;

    float4 acc[2][8];
#pragma unroll
    for (int tm = 0; tm < 2; ++tm)
#pragma unroll
        for (int tn = 0; tn < 8; ++tn)
            acc[tm][tn] = make_float4(0.f, 0.f, 0.f, 0.f);

    float4 pa[4], pb[4];
#pragma unroll
    for (int i = 0; i < 4; ++i) {
        int q = tid + i * 256;
        int row = q >> 3, chunk = q & 7;
        pa[i] = *reinterpret_cast<const float4*>(
            &x[(size_t)(m0 + row) * 512 + chunk * 4]);
        pb[i] = *reinterpret_cast<const float4*>(
            &Wih[(size_t)(n0 + row) * 512 + chunk * 4]);
    }

    for (int it = 0; it < 16; ++it) {
#pragma unroll
        for (int i = 0; i < 4; ++i) {
            int q = tid + i * 256;
            int row = q >> 3, chunk = q & 7;
            uint2 hi, lo;
            cvt_split(pa[i], hi, lo);
            *reinterpret_cast<uint2*>(&AsH[row * AST + chunk * 4]) = hi;
            *reinterpret_cast<uint2*>(&AsL[row * AST + chunk * 4]) = lo;
            cvt_split(pb[i], hi, lo);
            *reinterpret_cast<uint2*>(&BsH[row * AST + chunk * 4]) = hi;
            *reinterpret_cast<uint2*>(&BsL[row * AST + chunk * 4]) = lo;
        }
        __syncthreads();

        if (it < 15) {
            int k0 = (it + 1) * 32;
#pragma unroll
            for (int i = 0; i < 4; ++i) {
                int q = tid + i * 256;
                int row = q >> 3, chunk = q & 7;
                pa[i] = *reinterpret_cast<const float4*>(
                    &x[(size_t)(m0 + row) * 512 + k0 + chunk * 4]);
                pb[i] = *reinterpret_cast<const float4*>(
                    &Wih[(size_t)(n0 + row) * 512 + k0 + chunk * 4]);
            }
        }

#pragma unroll
        for (int ks = 0; ks < 2; ++ks) {
            const int cb = ks * 16 + t4 * 2;
            uint4 aH[2], aL[2];
#pragma unroll
            for (int tm = 0; tm < 2; ++tm) {
                int r = warp_m * 32 + tm * 16 + gq;
                aH[tm].x = *reinterpret_cast<const unsigned*>(&AsH[r * AST + cb]);
                aH[tm].y = *reinterpret_cast<const unsigned*>(&AsH[(r + 8) * AST + cb]);
                aH[tm].z = *reinterpret_cast<const unsigned*>(&AsH[r * AST + cb + 8]);
                aH[tm].w = *reinterpret_cast<const unsigned*>(&AsH[(r + 8) * AST + cb + 8]);
                aL[tm].x = *reinterpret_cast<const unsigned*>(&AsL[r * AST + cb]);
                aL[tm].y = *reinterpret_cast<const unsigned*>(&AsL[(r + 8) * AST + cb]);
                aL[tm].z = *reinterpret_cast<const unsigned*>(&AsL[r * AST + cb + 8]);
                aL[tm].w = *reinterpret_cast<const unsigned*>(&AsL[(r + 8) * AST + cb + 8]);
            }
#pragma unroll
            for (int tn = 0; tn < 8; ++tn) {
                int nr = warp_n * 64 + tn * 8 + gq;
                uint2 bH, bL;
                bH.x = *reinterpret_cast<const unsigned*>(&BsH[nr * AST + cb]);
                bH.y = *reinterpret_cast<const unsigned*>(&BsH[nr * AST + cb + 8]);
                bL.x = *reinterpret_cast<const unsigned*>(&BsL[nr * AST + cb]);
                bL.y = *reinterpret_cast<const unsigned*>(&BsL[nr * AST + cb + 8]);
#pragma unroll
                for (int tm = 0; tm < 2; ++tm) {
                    mma_bf16(acc[tm][tn], aH[tm], bH);
                    mma_bf16(acc[tm][tn], aH[tm], bL);
                    mma_bf16(acc[tm][tn], aL[tm], bH);
                }
            }
        }
        __syncthreads();
    }

#pragma unroll
    for (int tn = 0; tn < 8; ++tn) {
        int gn = n0 + warp_n * 64 + tn * 8 + t4 * 2;
        float b0 = bih[gn] + bhh[gn];
        float b1 = bih[gn + 1] + bhh[gn + 1];
#pragma unroll
        for (int tm = 0; tm < 2; ++tm) {
            int gm = m0 + warp_m * 32 + tm * 16 + gq;
            int t = gm & 511, b = gm >> 9;
            *reinterpret_cast<float2*>(
                &g_xg[((size_t)t * 32 + b) * 2048 + gn]) =
                make_float2(acc[tm][tn].x + b0, acc[tm][tn].y + b1);
            int gm2 = gm + 8;
            int t2 = gm2 & 511, b2 = gm2 >> 9;
            *reinterpret_cast<float2*>(
                &g_xg[((size_t)t2 * 32 + b2) * 2048 + gn]) =
                make_float2(acc[tm][tn].z + b0, acc[tm][tn].w + b1);
        }
    }
}

// =====================================================================
// Phase 2: dual-interleaved recurrence. 64 CTAs = 2 supergroups x 32.
// Each CTA: 16 j, two sets of 8 batches (A/B). R7 body per phase;
// set barrier armed at phase end, polled at next same-set phase start
// -> the other set's compute hides the sync+h-roundtrip latency.
// =====================================================================
#define HS_OFF   0
#define RED_OFF  18432
#define TGT_OFF  (18432 + 40960)
#define SMEM_REC_BYTES (TGT_OFF + 64)

// One phase of one set. Uses macro so tid/wid/etc. come from scope.
#define REC_PHASE(CSTATE, B0S, BPTR, TGTSLOT)                                   \
  do {                                                                          \
    float xi = 0.f, xf = 0.f, xz = 0.f, xo = 0.f;                               \
    if (tid < 128) {                                                            \
        const float* xp = &g_xg[((size_t)t * 32 + (B0S) + gb) * 2048 + J0 + jl];\
        xi = xp[0]; xf = xp[512]; xz = xp[1024]; xo = xp[1536];                 \
    }                                                                           \
    if (t) {                                                                    \
        if (tid == 0) {                                                         \
            unsigned tgt = tgts[TGTSLOT];                                       \
            unsigned cur;                                                       \
            asm volatile("ld.acquire.gpu.u32 %0, [%1];"                         \
                         : "=r"(cur) : "l"(BPTR) : "memory");                   \
            while (cur < tgt) {                                                 \
                __nanosleep(32);                                                \
                asm volatile("ld.acquire.gpu.u32 %0, [%1];"                     \
                             : "=r"(cur) : "l"(BPTR) : "memory");               \
            }                                                                   \
        }                                                                       \
        __syncthreads();                                                        \
        const float* hsrc = g_h[(t + 1) & 1];                                   \
        _Pragma("unroll")                                                       \
        for (int i = 0; i < 4; ++i) {                                           \
            int f   = tid + i * 512;                                            \
            int b   = f >> 8;                                                   \
            int rem = f & 255;                                                  \
            int d   = rem * 2;                                                  \
            int sli = d >> 4;                                                   \
            int m   = d & 15;                                                   \
            float2 v = *reinterpret_cast<const float2*>(                        \
                &hsrc[(size_t)((B0S) + b) * 512 + d]);                          \
            *reinterpret_cast<float2*>(&Hs[(b * 32 + sli) * 18 + m]) = v;       \
        }                                                                       \
    } else {                                                                    \
        _Pragma("unroll")                                                       \
        for (int i = 0; i < 4; ++i) {                                           \
            int f   = tid + i * 512;                                            \
            int b   = f >> 8;                                                   \
            int rem = f & 255;                                                  \
            int d   = rem * 2;                                                  \
            int sli = d >> 4;                                                   \
            int m   = d & 15;                                                   \
            *reinterpret_cast<float2*>(&Hs[(b * 32 + sli) * 18 + m]) =          \
                make_float2(0.f, 0.f);                                          \
        }                                                                       \
    }                                                                           \
    __syncthreads();                                                            \
    _Pragma("unroll")                                                           \
    for (int b = 0; b < 8; ++b) {                                               \
        const unsigned long long* hp =                                          \
            reinterpret_cast<const unsigned long long*>(&Hs[(b * 32 + sl) * 18]);\
        unsigned long long hb[8];                                               \
        _Pragma("unroll")                                                       \
        for (int k = 0; k < 8; ++k) hb[k] = hp[k];                              \
        unsigned long long ac[4];                                               \
        _Pragma("unroll")                                                       \
        for (int r = 0; r < 4; ++r) ac[r] = 0ULL;                               \
        _Pragma("unroll")                                                       \
        for (int k = 0; k < 8; ++k) {                                           \
            _Pragma("unroll")                                                   \
            for (int r = 0; r < 4; ++r) ffma2(ac[r], wreg[r][k], hb[k]);        \
        }                                                                       \
        _Pragma("unroll")                                                       \
        for (int r = 0; r < 4; ++r) {                                           \
            float lo, hi;                                                       \
            unpack2(ac[r], lo, hi);                                             \
            float s = lo + hi;                                                  \
            s += __shfl_xor_sync(0xffffffffu, s, 16);                           \
            if (sl < 16) Red[(b * 64 + wid * 4 + r) * 20 + sl] = s;             \
        }                                                                       \
    }                                                                           \
    __syncthreads();                                                            \
    if (tid < 128) {                                                            \
        float sums[4];                                                          \
        _Pragma("unroll")                                                       \
        for (int q = 0; q < 4; ++q) {                                           \
            const float4* rr = reinterpret_cast<const float4*>(                 \
                &Red[(gb * 64 + q * 16 + jl) * 20]);                            \
            float4 a = rr[0], bq = rr[1], cq = rr[2], dq = rr[3];               \
            sums[q] = ((a.x + a.y) + (a.z + a.w))                               \
                    + ((bq.x + bq.y) + (bq.z + bq.w))                           \
                    + ((cq.x + cq.y) + (cq.z + cq.w))                           \
                    + ((dq.x + dq.y) + (dq.z + dq.w));                          \
        }                                                                       \
        float ig = fast_sigmoid(xi + sums[0]);                                  \
        float fg = fast_sigmoid(xf + sums[1]);                                  \
        float gg = fast_tanh(xz + sums[2]);                                     \
        float og = fast_sigmoid(xo + sums[3]);                                  \
        CSTATE = fg * CSTATE + ig * gg;                                         \
        float hval = og * fast_tanh(CSTATE);                                    \
        g_h[t & 1][(size_t)((B0S) + gb) * 512 + J0 + jl] = hval;                \
        out[((size_t)((B0S) + gb) * 512 + t) * 512 + J0 + jl] = fmaxf(hval, 0.f);\
    }                                                                           \
    __syncthreads();                                                            \
    if (tid == 0) {                                                             \
        unsigned ticket;                                                        \
        asm volatile("atom.release.gpu.add.u32 %0, [%1], %2;"                   \
                     : "=r"(ticket) : "l"(BPTR), "r"(1u) : "memory");           \
        tgts[TGTSLOT] = (ticket / (unsigned)GCTAS + 1u) * (unsigned)GCTAS;      \
    }                                                                           \
  } while (0)

__global__ void __launch_bounds__(512, 1) lstm_rec_kernel(
    const float* __restrict__ Whh,
    float* __restrict__ out)
{
    extern __shared__ char smraw[];
    float* Hs  = reinterpret_cast<float*>(smraw + HS_OFF);
    float* Red = reinterpret_cast<float*>(smraw + RED_OFF);
    unsigned* tgts = reinterpret_cast<unsigned*>(smraw + TGT_OFF);

    const int tid  = threadIdx.x;
    const int sg   = blockIdx.x >> 5;           // supergroup 0..1
    const int rank = blockIdx.x & 31;
    const int B0A  = sg * 16;                   // set A batches
    const int B0B  = sg * 16 + 8;               // set B batches
    const int J0   = rank * 16;
    const int wid  = tid >> 5;
    const int sl   = tid & 31;

    unsigned long long wreg[4][8];
#pragma unroll
    for (int r = 0; r < 4; ++r) {
        int lr   = wid * 4 + r;
        int grow = (lr >> 4) * 512 + J0 + (lr & 15);
        const float2* wsrc = reinterpret_cast<const float2*>(
            &Whh[(size_t)grow * 512 + sl * 16]);
#pragma unroll
        for (int k = 0; k < 8; ++k) {
            float2 w2 = wsrc[k];
            wreg[r][k] = pack2(w2.x, w2.y);
        }
    }

    const int gb = tid >> 4;
    const int jl = tid & 15;
    float cA = 0.f, cB = 0.f;

    unsigned* bpA = &g_bar4[(sg * 2 + 0) * 32];
    unsigned* bpB = &g_bar4[(sg * 2 + 1) * 32];
    __syncthreads();

    for (int t = 0; t < TT; ++t) {
        REC_PHASE(cA, B0A, bpA, 0);
        REC_PHASE(cB, B0B, bpB, 1);
    }
}

extern "C" void kernel_launch(void* const* d_in, const int* in_sizes, int n_in,
                              void* d_out, int out_size)
{
    const float* x   = (const float*)d_in[0];
    const float* Wih = (const float*)d_in[1];
    const float* Whh = (const float*)d_in[2];
    const float* bih = (const float*)d_in[3];
    const float* bhh = (const float*)d_in[4];
    float* out = (float*)d_out;

    dim3 g1(128, 16);
    gemm_xg_mma<<<g1, 256>>>(x, Wih, bih, bhh);

    cudaFuncSetAttribute(lstm_rec_kernel,
                         cudaFuncAttributeMaxDynamicSharedMemorySize,
                         SMEM_REC_BYTES);
    lstm_rec_kernel<<<NCTA_REC, NTHR, SMEM_REC_BYTES>>>(Whh, out);
}

// round 15
// speedup vs baseline: 2.6877x; 2.6877x over previous
#include <cuda_runtime.h>
#include <cuda_bf16.h>
#include <cstdint>
#include <cstddef>

#define BSZ   32
#define TT    512
#define HH    512
#define G4    2048
#define GROUPS 4
#define GCTAS  32
#define BPG    8
#define NCTA  (GROUPS*GCTAS)
#define NTHR  512

// Device statics: identical set to passing R7/R13.
__device__ float g_xg[(size_t)TT * BSZ * G4];     // [T][B][4H]
__device__ float g_h[2][BSZ * HH];                // double-buffered h, [b][j]
__device__ unsigned g_bar4[GROUPS * 32];          // per-group barrier counters

__device__ __forceinline__ float fast_sigmoid(float x) {
    return __fdividef(1.f, 1.f + __expf(-x));
}
__device__ __forceinline__ float fast_tanh(float x) {
    x = fminf(fmaxf(x, -15.f), 15.f);
    float e2 = __expf(-2.f * x);
    return __fdividef(1.f - e2, 1.f + e2);
}

__device__ __forceinline__ void mma_bf16(float4& c, const uint4& a, const uint2& b) {
    asm("mma.sync.aligned.m16n8k16.row.col.f32.bf16.bf16.f32 "
        "{%0,%1,%2,%3}, {%4,%5,%6,%7}, {%8,%9}, {%0,%1,%2,%3};"
        : "+f"(c.x), "+f"(c.y), "+f"(c.z), "+f"(c.w)
        : "r"(a.x), "r"(a.y), "r"(a.z), "r"(a.w), "r"(b.x), "r"(b.y));
}

__device__ __forceinline__ void cvt_split(float4 v, uint2& hi, uint2& lo) {
    __nv_bfloat16 hx = __float2bfloat16(v.x);
    __nv_bfloat16 hy = __float2bfloat16(v.y);
    __nv_bfloat16 hz = __float2bfloat16(v.z);
    __nv_bfloat16 hw = __float2bfloat16(v.w);
    __nv_bfloat162 h01 = __halves2bfloat162(hx, hy);
    __nv_bfloat162 h23 = __halves2bfloat162(hz, hw);
    __nv_bfloat162 l01 = __halves2bfloat162(
        __float2bfloat16(v.x - __bfloat162float(hx)),
        __float2bfloat16(v.y - __bfloat162float(hy)));
    __nv_bfloat162 l23 = __halves2bfloat162(
        __float2bfloat16(v.z - __bfloat162float(hz)),
        __float2bfloat16(v.w - __bfloat162float(hw)));
    hi.x = *reinterpret_cast<unsigned*>(&h01);
    hi.y = *reinterpret_cast<unsigned*>(&h23);
    lo.x = *reinterpret_cast<unsigned*>(&l01);
    lo.y = *reinterpret_cast<unsigned*>(&l23);
}

__device__ __forceinline__ void split2(float2 v, unsigned& hi, unsigned& lo) {
    __nv_bfloat16 hx = __float2bfloat16(v.x);
    __nv_bfloat16 hy = __float2bfloat16(v.y);
    __nv_bfloat162 h = __halves2bfloat162(hx, hy);
    __nv_bfloat162 l = __halves2bfloat162(
        __float2bfloat16(v.x - __bfloat162float(hx)),
        __float2bfloat16(v.y - __bfloat162float(hy)));
    hi = *reinterpret_cast<unsigned*>(&h);
    lo = *reinterpret_cast<unsigned*>(&l);
}

// =====================================================================
// Phase 1: bf16x3 tensor-core GEMM with in-kernel split (R13, passed).
// =====================================================================
#define AST 40

__global__ void __launch_bounds__(256) gemm_xg_mma(
    const float* __restrict__ x,
    const float* __restrict__ Wih,
    const float* __restrict__ bih,
    const float* __restrict__ bhh)
{
    __shared__ __nv_bfloat16 AsH[128 * AST];
    __shared__ __nv_bfloat16 AsL[128 * AST];
    __shared__ __nv_bfloat16 BsH[128 * AST];
    __shared__ __nv_bfloat16 BsL[128 * AST];

    const int tid    = threadIdx.x;
    const int m0     = blockIdx.x * 128;
    const int n0     = blockIdx.y * 128;
    const int wid    = tid >> 5;
    const int lane   = tid & 31;
    const int warp_m = wid & 3;
    const int warp_n = wid >> 2;
    const int gq     = lane >> 2;
    const int t4     = lane & 3;

    float4 acc[2][8];
#pragma unroll
    for (int tm = 0; tm < 2; ++tm)
#pragma unroll
        for (int tn = 0; tn < 8; ++tn)
            acc[tm][tn] = make_float4(0.f, 0.f, 0.f, 0.f);

    float4 pa[4], pb[4];
#pragma unroll
    for (int i = 0; i < 4; ++i) {
        int q = tid + i * 256;
        int row = q >> 3, chunk = q & 7;
        pa[i] = *reinterpret_cast<const float4*>(
            &x[(size_t)(m0 + row) * 512 + chunk * 4]);
        pb[i] = *reinterpret_cast<const float4*>(
            &Wih[(size_t)(n0 + row) * 512 + chunk * 4]);
    }

    for (int it = 0; it < 16; ++it) {
#pragma unroll
        for (int i = 0; i < 4; ++i) {
            int q = tid + i * 256;
            int row = q >> 3, chunk = q & 7;
            uint2 hi, lo;
            cvt_split(pa[i], hi, lo);
            *reinterpret_cast<uint2*>(&AsH[row * AST + chunk * 4]) = hi;
            *reinterpret_cast<uint2*>(&AsL[row * AST + chunk * 4]) = lo;
            cvt_split(pb[i], hi, lo);
            *reinterpret_cast<uint2*>(&BsH[row * AST + chunk * 4]) = hi;
            *reinterpret_cast<uint2*>(&BsL[row * AST + chunk * 4]) = lo;
        }
        __syncthreads();

        if (it < 15) {
            int k0 = (it + 1) * 32;
#pragma unroll
            for (int i = 0; i < 4; ++i) {
                int q = tid + i * 256;
                int row = q >> 3, chunk = q & 7;
                pa[i] = *reinterpret_cast<const float4*>(
                    &x[(size_t)(m0 + row) * 512 + k0 + chunk * 4]);
                pb[i] = *reinterpret_cast<const float4*>(
                    &Wih[(size_t)(n0 + row) * 512 + k0 + chunk * 4]);
            }
        }

#pragma unroll
        for (int ks = 0; ks < 2; ++ks) {
            const int cb = ks * 16 + t4 * 2;
            uint4 aH[2], aL[2];
#pragma unroll
            for (int tm = 0; tm < 2; ++tm) {
                int r = warp_m * 32 + tm * 16 + gq;
                aH[tm].x = *reinterpret_cast<const unsigned*>(&AsH[r * AST + cb]);
                aH[tm].y = *reinterpret_cast<const unsigned*>(&AsH[(r + 8) * AST + cb]);
                aH[tm].z = *reinterpret_cast<const unsigned*>(&AsH[r * AST + cb + 8]);
                aH[tm].w = *reinterpret_cast<const unsigned*>(&AsH[(r + 8) * AST + cb + 8]);
                aL[tm].x = *reinterpret_cast<const unsigned*>(&AsL[r * AST + cb]);
                aL[tm].y = *reinterpret_cast<const unsigned*>(&AsL[(r + 8) * AST + cb]);
                aL[tm].z = *reinterpret_cast<const unsigned*>(&AsL[r * AST + cb + 8]);
                aL[tm].w = *reinterpret_cast<const unsigned*>(&AsL[(r + 8) * AST + cb + 8]);
            }
#pragma unroll
            for (int tn = 0; tn < 8; ++tn) {
                int nr = warp_n * 64 + tn * 8 + gq;
                uint2 bH, bL;
                bH.x = *reinterpret_cast<const unsigned*>(&BsH[nr * AST + cb]);
                bH.y = *reinterpret_cast<const unsigned*>(&BsH[nr * AST + cb + 8]);
                bL.x = *reinterpret_cast<const unsigned*>(&BsL[nr * AST + cb]);
                bL.y = *reinterpret_cast<const unsigned*>(&BsL[nr * AST + cb + 8]);
#pragma unroll
                for (int tm = 0; tm < 2; ++tm) {
                    mma_bf16(acc[tm][tn], aH[tm], bH);
                    mma_bf16(acc[tm][tn], aH[tm], bL);
                    mma_bf16(acc[tm][tn], aL[tm], bH);
                }
            }
        }
        __syncthreads();
    }

#pragma unroll
    for (int tn = 0; tn < 8; ++tn) {
        int gn = n0 + warp_n * 64 + tn * 8 + t4 * 2;
        float b0 = bih[gn] + bhh[gn];
        float b1 = bih[gn + 1] + bhh[gn + 1];
#pragma unroll
        for (int tm = 0; tm < 2; ++tm) {
            int gm = m0 + warp_m * 32 + tm * 16 + gq;
            int t = gm & 511, b = gm >> 9;
            *reinterpret_cast<float2*>(
                &g_xg[((size_t)t * 32 + b) * 2048 + gn]) =
                make_float2(acc[tm][tn].x + b0, acc[tm][tn].y + b1);
            int gm2 = gm + 8;
            int t2 = gm2 & 511, b2 = gm2 >> 9;
            *reinterpret_cast<float2*>(
                &g_xg[((size_t)t2 * 32 + b2) * 2048 + gn]) =
                make_float2(acc[tm][tn].z + b0, acc[tm][tn].w + b1);
        }
    }
}

// =====================================================================
// Phase 2: HMMA recurrence. 128 CTAs (4 groups x 32), R13 barrier/xg/h.
// Warp (mg: gate tile of 16 j, ks: K-split of 128). W bf16x3 fragments
// register-resident. h staged per step as packed bf16 hi/lo pair-words.
// 24 mma/warp/step; K-reduce via small smem scatter; gates on tid<128.
// =====================================================================
#define HB_STRIDE 260           // uints per batch (256 pairs + pad) -> conflict-free
#define RED_RS    9
#define RED_PLANE 149

__global__ void __launch_bounds__(512, 1) lstm_rec_kernel(
    const float* __restrict__ Whh,
    float* __restrict__ out)
{
    __shared__ unsigned HsH[8 * HB_STRIDE];     // h hi pairs [b][pair]
    __shared__ unsigned HsL[8 * HB_STRIDE];     // h lo pairs
    __shared__ float Red[16 * RED_PLANE];       // per-warp C fragments

    const int tid   = threadIdx.x;
    const int group = blockIdx.x >> 5;
    const int rank  = blockIdx.x & 31;
    const int B0    = group * BPG;
    const int J0    = rank * 16;
    const int wid   = tid >> 5;
    const int lane  = tid & 31;
    const int mg    = wid & 3;                  // gate (i,f,g,o)
    const int ks    = wid >> 2;                 // K-split 0..3 (128 each)
    const int gq    = lane >> 2;
    const int t4    = lane & 3;

    // ---- W bf16x3 fragments into registers (A row-major, GEMM convention) ----
    uint4 wAH[8], wAL[8];
#pragma unroll
    for (int kk = 0; kk < 8; ++kk) {
        int cb = ks * 128 + kk * 16 + t4 * 2;
        int g1 = mg * 512 + J0 + gq;            // rows gq and gq+8 of this tile
        int g2 = g1 + 8;
        float2 v1a = *reinterpret_cast<const float2*>(&Whh[(size_t)g1 * 512 + cb]);
        float2 v2a = *reinterpret_cast<const float2*>(&Whh[(size_t)g2 * 512 + cb]);
        float2 v1b = *reinterpret_cast<const float2*>(&Whh[(size_t)g1 * 512 + cb + 8]);
        float2 v2b = *reinterpret_cast<const float2*>(&Whh[(size_t)g2 * 512 + cb + 8]);
        split2(v1a, wAH[kk].x, wAL[kk].x);
        split2(v2a, wAH[kk].y, wAL[kk].y);
        split2(v1b, wAH[kk].z, wAL[kk].z);
        split2(v2b, wAH[kk].w, wAL[kk].w);
    }

    const int gb = tid >> 4;         // gate-thread batch (tid<128)
    const int jl = tid & 15;         // gate-thread hidden index (local)
    float c = 0.f;

    unsigned* bp = &g_bar4[group * 32];
    __syncthreads();

    for (int t = 0; t < TT; ++t) {
        // xg prefetch (independent of barrier)
        float xi = 0.f, xf = 0.f, xz = 0.f, xo = 0.f;
        if (tid < 128) {
            const float* xp = &g_xg[((size_t)t * 32 + B0 + gb) * 2048 + J0 + jl];
            xi = xp[0]; xf = xp[512]; xz = xp[1024]; xo = xp[1536];
        }

        if (t) {
            __syncthreads();         // Red reads + h writes of t-1 done
            if (tid == 0) {
                unsigned ticket;
                asm volatile("atom.release.gpu.add.u32 %0, [%1], %2;"
                             : "=r"(ticket) : "l"(bp), "r"(1u) : "memory");
                unsigned target = (ticket / (unsigned)GCTAS + 1u) * (unsigned)GCTAS;
                unsigned cur;
                asm volatile("ld.acquire.gpu.u32 %0, [%1];"
                             : "=r"(cur) : "l"(bp) : "memory");
                while (cur < target) {
                    __nanosleep(32);
                    asm volatile("ld.acquire.gpu.u32 %0, [%1];"
                                 : "=r"(cur) : "l"(bp) : "memory");
                }
            }
            __syncthreads();

            // stage h_{t-1}: convert to bf16 hi/lo pair-words
            const float* hsrc = g_h[(t + 1) & 1];
#pragma unroll
            for (int i = 0; i < 4; ++i) {
                int p  = tid + i * 512;          // pair index 0..2047
                int b  = p >> 8;
                int pp = p & 255;
                float2 v = *reinterpret_cast<const float2*>(
                    &hsrc[(size_t)(B0 + b) * 512 + pp * 2]);
                unsigned hi, lo;
                split2(v, hi, lo);
                HsH[b * HB_STRIDE + pp] = hi;
                HsL[b * HB_STRIDE + pp] = lo;
            }
        } else {
#pragma unroll
            for (int i = 0; i < 4; ++i) {
                int p  = tid + i * 512;
                int b  = p >> 8;
                int pp = p & 255;
                HsH[b * HB_STRIDE + pp] = 0u;
                HsL[b * HB_STRIDE + pp] = 0u;
            }
        }
        __syncthreads();

        // ---- mma chain: 8 k-steps x 3 products ----
        float4 acc = make_float4(0.f, 0.f, 0.f, 0.f);
#pragma unroll
        for (int kk = 0; kk < 8; ++kk) {
            int P0 = ks * 64 + kk * 8 + t4;
            uint2 bH, bL;
            bH.x = HsH[gq * HB_STRIDE + P0];
            bH.y = HsH[gq * HB_STRIDE + P0 + 4];
            bL.x = HsL[gq * HB_STRIDE + P0];
            bL.y = HsL[gq * HB_STRIDE + P0 + 4];
            mma_bf16(acc, wAH[kk], bH);
            mma_bf16(acc, wAH[kk], bL);
            mma_bf16(acc, wAL[kk], bH);
        }
        {
            int plane = (mg * 4 + ks) * RED_PLANE;
            Red[plane + gq * RED_RS + t4 * 2]           = acc.x;
            Red[plane + gq * RED_RS + t4 * 2 + 1]       = acc.y;
            Red[plane + (gq + 8) * RED_RS + t4 * 2]     = acc.z;
            Red[plane + (gq + 8) * RED_RS + t4 * 2 + 1] = acc.w;
        }
        __syncthreads();

        // ---- K-reduce + gates (128 threads: (gb, jl)) ----
        if (tid < 128) {
            float s[4];
#pragma unroll
            for (int m = 0; m < 4; ++m) {
                int off = jl * RED_RS + gb;
                s[m] = Red[(m * 4 + 0) * RED_PLANE + off]
                     + Red[(m * 4 + 1) * RED_PLANE + off]
                     + Red[(m * 4 + 2) * RED_PLANE + off]
                     + Red[(m * 4 + 3) * RED_PLANE + off];
            }
            float ig = fast_sigmoid(xi + s[0]);
            float fg = fast_sigmoid(xf + s[1]);
            float gg = fast_tanh(xz + s[2]);
            float og = fast_sigmoid(xo + s[3]);
            c = fg * c + ig * gg;
            float hval = og * fast_tanh(c);
            g_h[t & 1][(size_t)(B0 + gb) * 512 + J0 + jl] = hval;
            out[((size_t)(B0 + gb) * 512 + t) * 512 + J0 + jl] = fmaxf(hval, 0.f);
        }
    }
}

extern "C" void kernel_launch(void* const* d_in, const int* in_sizes, int n_in,
                              void* d_out, int out_size)
{
    const float* x   = (const float*)d_in[0];
    const float* Wih = (const float*)d_in[1];
    const float* Whh = (const float*)d_in[2];
    const float* bih = (const float*)d_in[3];
    const float* bhh = (const float*)d_in[4];
    float* out = (float*)d_out;

    dim3 g1(128, 16);
    gemm_xg_mma<<<g1, 256>>>(x, Wih, bih, bhh);

    lstm_rec_kernel<<<NCTA, NTHR>>>(Whh, out);
}

// round 16
// speedup vs baseline: 2.6915x; 1.0014x over previous
#include <cuda_runtime.h>
#include <cuda_bf16.h>
#include <cstdint>
#include <cstddef>

#define BSZ   32
#define TT    512
#define HH    512
#define G4    2048
#define GROUPS 4
#define GCTAS  32
#define BPG    8
#define NCTA  (GROUPS*GCTAS)
#define NTHR  512

// Device statics: byte-identical set to passing R15 (g_xg kept though unused).
__device__ float g_xg[(size_t)TT * BSZ * G4];
__device__ float g_h[2][BSZ * HH];                // double-buffered h, [b][j]
__device__ unsigned g_bar4[GROUPS * 32];          // per-group barrier counters

__device__ __forceinline__ float fast_sigmoid(float x) {
    return __fdividef(1.f, 1.f + __expf(-x));
}
__device__ __forceinline__ float fast_tanh(float x) {
    x = fminf(fmaxf(x, -15.f), 15.f);
    float e2 = __expf(-2.f * x);
    return __fdividef(1.f - e2, 1.f + e2);
}

__device__ __forceinline__ void mma_bf16(float4& c, const uint4& a, const uint2& b) {
    asm("mma.sync.aligned.m16n8k16.row.col.f32.bf16.bf16.f32 "
        "{%0,%1,%2,%3}, {%4,%5,%6,%7}, {%8,%9}, {%0,%1,%2,%3};"
        : "+f"(c.x), "+f"(c.y), "+f"(c.z), "+f"(c.w)
        : "r"(a.x), "r"(a.y), "r"(a.z), "r"(a.w), "r"(b.x), "r"(b.y));
}

__device__ __forceinline__ void split2(float2 v, unsigned& hi, unsigned& lo) {
    __nv_bfloat16 hx = __float2bfloat16(v.x);
    __nv_bfloat16 hy = __float2bfloat16(v.y);
    __nv_bfloat162 h = __halves2bfloat162(hx, hy);
    __nv_bfloat162 l = __halves2bfloat162(
        __float2bfloat16(v.x - __bfloat162float(hx)),
        __float2bfloat16(v.y - __bfloat162float(hy)));
    hi = *reinterpret_cast<unsigned*>(&h);
    lo = *reinterpret_cast<unsigned*>(&l);
}

// =====================================================================
// Fused kernel: input projection (bf16x3 HMMA vs W_ih smem slice) +
// recurrence (bf16x3 HMMA vs register-resident W_hh), one acc chain.
// 128 CTAs (4 groups x 32). CTA: 16 j, 8 batches. R15 barrier verbatim.
//
// smem (uints):
//   WiH[64*260] WiL[64*260]            W_ih slice hi/lo pair-words
//   XsH/XsL[8*260]                     x_t pair-words
//   HsH/HsL[8*260]                     h_{t-1} pair-words
//   Red (float[16*149])                per-warp C fragments
// =====================================================================
#define PSTR  260
#define WI_E  (64 * PSTR)
#define RED_RS    9
#define RED_PLANE 149
#define OFF_WIH 0
#define OFF_WIL (WI_E)
#define OFF_XSH (2 * WI_E)
#define OFF_XSL (2 * WI_E + 8 * PSTR)
#define OFF_HSH (2 * WI_E + 16 * PSTR)
#define OFF_HSL (2 * WI_E + 24 * PSTR)
#define OFF_RED (2 * WI_E + 32 * PSTR)
#define SMEM_UINTS (OFF_RED + 16 * RED_PLANE)
#define SMEM_REC_BYTES (SMEM_UINTS * 4)

__global__ void __launch_bounds__(512, 1) lstm_fused_kernel(
    const float* __restrict__ x,
    const float* __restrict__ Wih,
    const float* __restrict__ Whh,
    const float* __restrict__ bih,
    const float* __restrict__ bhh,
    float* __restrict__ out)
{
    extern __shared__ unsigned smu[];
    unsigned* WiH = smu + OFF_WIH;
    unsigned* WiL = smu + OFF_WIL;
    unsigned* XsH = smu + OFF_XSH;
    unsigned* XsL = smu + OFF_XSL;
    unsigned* HsH = smu + OFF_HSH;
    unsigned* HsL = smu + OFF_HSL;
    float*    Red = reinterpret_cast<float*>(smu + OFF_RED);

    const int tid   = threadIdx.x;
    const int group = blockIdx.x >> 5;
    const int rank  = blockIdx.x & 31;
    const int B0    = group * BPG;
    const int J0    = rank * 16;
    const int wid   = tid >> 5;
    const int lane  = tid & 31;
    const int mg    = wid & 3;                  // gate tile (i,f,g,o)
    const int ks    = wid >> 2;                 // K-split 0..3
    const int gq    = lane >> 2;
    const int t4    = lane & 3;

    // ---- W_ih slice -> smem hi/lo pair-words. Local row = q*16 + jl. ----
    for (int i = 0; i < 32; ++i) {
        int idx = tid + i * 512;                // 0..16383 pairs
        int row = idx >> 8;                     // 0..63
        int pp  = idx & 255;
        int g   = (row >> 4) * 512 + J0 + (row & 15);
        float2 v = *reinterpret_cast<const float2*>(&Wih[(size_t)g * 512 + pp * 2]);
        unsigned hi, lo;
        split2(v, hi, lo);
        WiH[row * PSTR + pp] = hi;
        WiL[row * PSTR + pp] = lo;
    }

    // ---- W_hh bf16x3 fragments -> registers (R15 convention) ----
    uint4 wAH[8], wAL[8];
#pragma unroll
    for (int kk = 0; kk < 8; ++kk) {
        int cb = ks * 128 + kk * 16 + t4 * 2;
        int g1 = mg * 512 + J0 + gq;
        int g2 = g1 + 8;
        float2 v1a = *reinterpret_cast<const float2*>(&Whh[(size_t)g1 * 512 + cb]);
        float2 v2a = *reinterpret_cast<const float2*>(&Whh[(size_t)g2 * 512 + cb]);
        float2 v1b = *reinterpret_cast<const float2*>(&Whh[(size_t)g1 * 512 + cb + 8]);
        float2 v2b = *reinterpret_cast<const float2*>(&Whh[(size_t)g2 * 512 + cb + 8]);
        split2(v1a, wAH[kk].x, wAL[kk].x);
        split2(v2a, wAH[kk].y, wAL[kk].y);
        split2(v1b, wAH[kk].z, wAL[kk].z);
        split2(v2b, wAH[kk].w, wAL[kk].w);
    }

    const int gb = tid >> 4;          // gate-thread batch (tid<128)
    const int jl = tid & 15;          // gate-thread hidden index (local)
    float c = 0.f;
    float bias0 = 0.f, bias1 = 0.f, bias2 = 0.f, bias3 = 0.f;
    if (tid < 128) {
        bias0 = bih[J0 + jl]        + bhh[J0 + jl];
        bias1 = bih[512 + J0 + jl]  + bhh[512 + J0 + jl];
        bias2 = bih[1024 + J0 + jl] + bhh[1024 + J0 + jl];
        bias3 = bih[1536 + J0 + jl] + bhh[1536 + J0 + jl];
    }

    unsigned* bp = &g_bar4[group * 32];
    __syncthreads();

    for (int t = 0; t < TT; ++t) {
        // ---- stage x_t (no peer dependency) ----
#pragma unroll
        for (int i = 0; i < 4; ++i) {
            int p  = tid + i * 512;
            int b  = p >> 8;
            int pp = p & 255;
            float2 v = *reinterpret_cast<const float2*>(
                &x[((size_t)(B0 + b) * 512 + t) * 512 + pp * 2]);
            unsigned hi, lo;
            split2(v, hi, lo);
            XsH[b * PSTR + pp] = hi;
            XsL[b * PSTR + pp] = lo;
        }
        __syncthreads();    // (A) x staged; prior-step g_h/out writes done

        // arrive early (t>0): peers can see our t-1 completion while we x-mma
        if (t && tid == 0) {
            unsigned ticket;
            asm volatile("atom.release.gpu.add.u32 %0, [%1], %2;"
                         : "=r"(ticket) : "l"(bp), "r"(1u) : "memory");
            // stash target in Red[0]-adjacent? keep in register:
            // store into shared slot via st below
            reinterpret_cast<unsigned*>(Red)[RED_PLANE * 16 - 1] =
                (ticket / (unsigned)GCTAS + 1u) * (unsigned)GCTAS;
        }

        // ---- x-mma: A = W_ih smem frags, B = x frags ----
        float4 acc = make_float4(0.f, 0.f, 0.f, 0.f);
#pragma unroll
        for (int kk = 0; kk < 8; ++kk) {
            int p0 = ks * 64 + kk * 8 + t4;
            int r1 = (mg * 16 + gq) * PSTR;
            int r2 = (mg * 16 + gq + 8) * PSTR;
            uint4 aH, aL;
            aH.x = WiH[r1 + p0]; aH.y = WiH[r2 + p0];
            aH.z = WiH[r1 + p0 + 4]; aH.w = WiH[r2 + p0 + 4];
            aL.x = WiL[r1 + p0]; aL.y = WiL[r2 + p0];
            aL.z = WiL[r1 + p0 + 4]; aL.w = WiL[r2 + p0 + 4];
            uint2 bH, bL;
            bH.x = XsH[gq * PSTR + p0];
            bH.y = XsH[gq * PSTR + p0 + 4];
            bL.x = XsL[gq * PSTR + p0];
            bL.y = XsL[gq * PSTR + p0 + 4];
            mma_bf16(acc, aH, bH);
            mma_bf16(acc, aH, bL);
            mma_bf16(acc, aL, bH);
        }

        if (t) {
            if (tid == 0) {
                unsigned target =
                    reinterpret_cast<unsigned*>(Red)[RED_PLANE * 16 - 1];
                unsigned cur;
                asm volatile("ld.acquire.gpu.u32 %0, [%1];"
                             : "=r"(cur) : "l"(bp) : "memory");
                while (cur < target) {
                    __nanosleep(32);
                    asm volatile("ld.acquire.gpu.u32 %0, [%1];"
                                 : "=r"(cur) : "l"(bp) : "memory");
                }
            }
            __syncthreads();   // (B) barrier passed

            // stage h_{t-1}
            const float* hsrc = g_h[(t + 1) & 1];
#pragma unroll
            for (int i = 0; i < 4; ++i) {
                int p  = tid + i * 512;
                int b  = p >> 8;
                int pp = p & 255;
                float2 v = *reinterpret_cast<const float2*>(
                    &hsrc[(size_t)(B0 + b) * 512 + pp * 2]);
                unsigned hi, lo;
                split2(v, hi, lo);
                HsH[b * PSTR + pp] = hi;
                HsL[b * PSTR + pp] = lo;
            }
        } else {
#pragma unroll
            for (int i = 0; i < 4; ++i) {
                int p  = tid + i * 512;
                int b  = p >> 8;
                int pp = p & 255;
                HsH[b * PSTR + pp] = 0u;
                HsL[b * PSTR + pp] = 0u;
            }
        }
        __syncthreads();       // (C) h staged

        // ---- h-mma into same acc: A = register W_hh frags ----
#pragma unroll
        for (int kk = 0; kk < 8; ++kk) {
            int p0 = ks * 64 + kk * 8 + t4;
            uint2 bH, bL;
            bH.x = HsH[gq * PSTR + p0];
            bH.y = HsH[gq * PSTR + p0 + 4];
            bL.x = HsL[gq * PSTR + p0];
            bL.y = HsL[gq * PSTR + p0 + 4];
            mma_bf16(acc, wAH[kk], bH);
            mma_bf16(acc, wAH[kk], bL);
            mma_bf16(acc, wAL[kk], bH);
        }
        {
            int plane = (mg * 4 + ks) * RED_PLANE;
            Red[plane + gq * RED_RS + t4 * 2]           = acc.x;
            Red[plane + gq * RED_RS + t4 * 2 + 1]       = acc.y;
            Red[plane + (gq + 8) * RED_RS + t4 * 2]     = acc.z;
            Red[plane + (gq + 8) * RED_RS + t4 * 2 + 1] = acc.w;
        }
        __syncthreads();       // (D) Red complete

        // ---- K-reduce + gates ----
        if (tid < 128) {
            float s[4];
#pragma unroll
            for (int m = 0; m < 4; ++m) {
                int off = jl * RED_RS + gb;
                s[m] = Red[(m * 4 + 0) * RED_PLANE + off]
                     + Red[(m * 4 + 1) * RED_PLANE + off]
                     + Red[(m * 4 + 2) * RED_PLANE + off]
                     + Red[(m * 4 + 3) * RED_PLANE + off];
            }
            float ig = fast_sigmoid(bias0 + s[0]);
            float fg = fast_sigmoid(bias1 + s[1]);
            float gg = fast_tanh(bias2 + s[2]);
            float og = fast_sigmoid(bias3 + s[3]);
            c = fg * c + ig * gg;
            float hval = og * fast_tanh(c);
            g_h[t & 1][(size_t)(B0 + gb) * 512 + J0 + jl] = hval;
            out[((size_t)(B0 + gb) * 512 + t) * 512 + J0 + jl] = fmaxf(hval, 0.f);
        }
    }
}

extern "C" void kernel_launch(void* const* d_in, const int* in_sizes, int n_in,
                              void* d_out, int out_size)
{
    const float* x   = (const float*)d_in[0];
    const float* Wih = (const float*)d_in[1];
    const float* Whh = (const float*)d_in[2];
    const float* bih = (const float*)d_in[3];
    const float* bhh = (const float*)d_in[4];
    float* out = (float*)d_out;

    cudaFuncSetAttribute(lstm_fused_kernel,
                         cudaFuncAttributeMaxDynamicSharedMemorySize,
                         SMEM_REC_BYTES);
    lstm_fused_kernel<<<NCTA, NTHR, SMEM_REC_BYTES>>>(x, Wih, Whh, bih, bhh, out);
}